// round 5
// baseline (speedup 1.0000x reference)
#include <cuda_runtime.h>
#include <cuda_bf16.h>
#include <math.h>

// Problem constants (fixed by reference)
#define N_MOL  2048
#define P_PRO  2048
#define HID    64
#define HEADS  16
#define NGRAPH 64
#define NGRID  128          // sampled-grid entries per head (every 16th element)

// ---------------- scratch (device globals; allocations are forbidden) -------
__device__ float  g_sortedB[HEADS][P_PRO];      // per-head ascending-sorted a_pro
__device__ float2 g_pref2[HEADS][P_PRO + 1];    // {prefix(b), prefix(exp b)} exclusive
__device__ float  g_grid[HEADS][NGRID];         // g_grid[h][i] = sorted[h][16i+15]

// Warp compare-exchange via shfl_xor for element whose index-bits[0:4] == lane.
__device__ __forceinline__ float cmpex_shfl(float v, int j, bool dir, int lane) {
    float p = __shfl_xor_sync(0xFFFFFFFF, v, j);
    bool lower = ((lane & j) == 0);
    return (lower == dir) ? fminf(v, p) : fmaxf(v, p);
}

// ============================================================================
// K1: one block per head. Projection a_pro -> hybrid bitonic sort ->
// fp32 prefix sums + sampled grid. 1024 threads.
// Sort element mapping: thread t = w*32+lane holds ia = w*64+lane, ib = ia+32.
// Phases j<=16 via shfl, j==32 in-register, j>=64 via smem (15 phases total).
// ============================================================================
__global__ __launch_bounds__(1024, 1)
void head_kernel(const float* __restrict__ pro,      // [2048,64]
                 const float* __restrict__ Wmu) {    // [128,16] row-major
    const int h    = blockIdx.x;
    const int t    = threadIdx.x;
    const int lane = t & 31;
    const int w    = t >> 5;
    const int ia   = w * 64 + lane;
    const int ib   = ia + 32;

    __shared__ float wv[HID];
    __shared__ float sb[P_PRO];
    __shared__ float warpB[33];
    __shared__ float warpE[33];

    if (t < HID) wv[t] = Wmu[(HID + t) * HEADS + h];   // protein half of Wmu, col h
    __syncthreads();

    // projection: this thread's two elements straight into registers
    float a, b;
    {
        const float* fa = pro + ia * HID;
        const float* fb = pro + ib * HID;
        float accA = 0.f, accB = 0.f;
#pragma unroll
        for (int k = 0; k < HID; k++) {
            float wk = wv[k];
            accA = fmaf(__ldg(fa + k), wk, accA);
            accB = fmaf(__ldg(fb + k), wk, accB);
        }
        a = accA; b = accB;
    }

    // ---------------- hybrid bitonic sort (ascending) ----------------------
    for (int k = 2; k <= P_PRO; k <<= 1) {
        const bool dira = ((ia & k) == 0);
        const bool dirb = ((ib & k) == 0);

        if (k >= 128) {
            // smem phases: j = k/2 down to 64
            sb[ia] = a; sb[ib] = b;
            __syncthreads();
            for (int j = k >> 1; j >= 64; j >>= 1) {
                int i   = ((t & ~(j - 1)) << 1) | (t & (j - 1));  // bit-j = 0
                int ixj = i | j;
                bool dir = ((i & k) == 0);
                float x = sb[i], y = sb[ixj];
                if ((x > y) == dir) { sb[i] = y; sb[ixj] = x; }
                __syncthreads();
            }
            a = sb[ia]; b = sb[ib];
        }
        if (k >= 64) {
            // j = 32: partner is this thread's other register (pair lower = ia)
            float lo = fminf(a, b), hi = fmaxf(a, b);
            a = dira ? lo : hi;
            b = dira ? hi : lo;
        }
        // j = min(k/2,16) .. 1 : shfl phases
        int j0 = (k >> 1) < 16 ? (k >> 1) : 16;
        for (int j = j0; j >= 1; j >>= 1) {
            a = cmpex_shfl(a, j, dira, lane);
            b = cmpex_shfl(b, j, dirb, lane);
        }
    }
    // park sorted values in smem in index order
    sb[ia] = a; sb[ib] = b;
    __syncthreads();

    // ---------------- fp32 prefix sums of b and exp(b) ----------------------
    // Thread t owns elements 2t, 2t+1. Fixed structure -> deterministic.
    float b0 = sb[2 * t];
    float b1 = sb[2 * t + 1];
    float e0 = __expf(b0), e1 = __expf(b1);
    float tB = b0 + b1, tE = e0 + e1;

    float sB = tB, sE = tE;   // warp inclusive scan
#pragma unroll
    for (int d = 1; d < 32; d <<= 1) {
        float uB = __shfl_up_sync(0xFFFFFFFF, sB, d);
        float uE = __shfl_up_sync(0xFFFFFFFF, sE, d);
        if (lane >= d) { sB += uB; sE += uE; }
    }
    if (lane == 31) { warpB[w] = sB; warpE[w] = sE; }
    __syncthreads();
    if (w == 0) {
        float vB = warpB[lane], vE = warpE[lane];
#pragma unroll
        for (int d = 1; d < 32; d <<= 1) {
            float uB = __shfl_up_sync(0xFFFFFFFF, vB, d);
            float uE = __shfl_up_sync(0xFFFFFFFF, vE, d);
            if (lane >= d) { vB += uB; vE += uE; }
        }
        warpB[lane + 1] = vB;   // warpB[w+1] = inclusive sum of warps 0..w
        warpE[lane + 1] = vE;
        if (lane == 0) { warpB[0] = 0.f; warpE[0] = 0.f; }
    }
    __syncthreads();

    float offB = warpB[w] + (sB - tB);   // exclusive offset for this thread
    float offE = warpE[w] + (sE - tE);

    g_pref2[h][2 * t + 1] = make_float2(offB + b0,      offE + e0);
    g_pref2[h][2 * t + 2] = make_float2(offB + b0 + b1, offE + e0 + e1);
    if (t == 0) g_pref2[h][0] = make_float2(0.f, 0.f);

    for (int i = t; i < P_PRO; i += 1024)
        g_sortedB[h][i] = sb[i];
    if (t < NGRID)
        g_grid[h][t] = sb[t * 16 + 15];
}

// ============================================================================
// K2: one block per graph. Finds the graph's contiguous atom range in the
// sorted mol_batch, computes a_mol inline, evaluates the closed-form
// reduction via a two-level search (8 smem grid levels + 4 L2 refine levels,
// two atoms interleaved for MLP=2), segment-sums deterministically, applies
// the MLP head. 256 threads.
// ============================================================================
__global__ __launch_bounds__(256, 1)
void graph_kernel(const float* __restrict__ mol,       // [2048,64]
                  const float* __restrict__ Wmu,       // [128,16]
                  const float* __restrict__ bmu,       // [16]
                  const int*   __restrict__ raw,       // mol_batch (i32 or i64 words)
                  const float* __restrict__ W1,        // [16,32]
                  const float* __restrict__ b1,        // [32]
                  const float* __restrict__ W2,        // [32,1]
                  const float* __restrict__ b2,        // [1]
                  float*       __restrict__ out) {     // [64]
    const int g = blockIdx.x;
    const int t = threadIdx.x;

    __shared__ float wm[HID * HEADS];          // mol half of Wmu, [k*16+h]
    __shared__ float sgrid[HEADS * NGRID];     // sampled grids, 8KB
    __shared__ float sbmu[HEADS];
    __shared__ float part[256];
    __shared__ float yg[HEADS];
    __shared__ float h2[2 * HEADS];

    for (int i = t; i < HID * HEADS; i += 256) wm[i] = Wmu[i];
    for (int i = t; i < HEADS * NGRID; i += 256)
        sgrid[i] = ((const float*)g_grid)[i];
    if (t < HEADS) sbmu[t] = bmu[t];
    __syncthreads();

    // int64 vs int32 layout of mol_batch: for little-endian int64, word 2047
    // is the high half of element 1023 (== 0, values are small non-negative);
    // for int32 it is the last (max) batch id, nonzero for this distribution.
    const bool is64 = (raw[N_MOL - 1] == 0);
    const int  stride = is64 ? 2 : 1;

    // contiguous range [start, end) of atoms with batch == g (batch is sorted)
    int lo = 0, hi = N_MOL;
    while (lo < hi) { int m = (lo + hi) >> 1; if (raw[m * stride] < g) lo = m + 1; else hi = m; }
    const int start = lo;
    lo = start; hi = N_MOL;
    while (lo < hi) { int m = (lo + hi) >> 1; if (raw[m * stride] < g + 1) lo = m + 1; else hi = m; }
    const int end = lo;

    // y_atom closed form. Thread t: head h = t&15, atom chunk c = t>>4.
    const int h = t & (HEADS - 1);
    const int c = t >> 4;
    float acc = 0.f;
    const float*  sbp = g_sortedB[h];
    const float2* pr  = g_pref2[h];
    const float*  sg  = sgrid + h * NGRID;
    const float   totB = pr[P_PRO].x;

    // two-level count: p = #{j : b_j <= na}.
    //   level 1 (smem): q = #{i : grid[i] <= na} over 128 samples (grid[i] =
    //   max of block i), so p in [16q, 16q+15] (grid[q] > na bounds the window).
    //   level 2 (L2): uniform steps 8,4,2,1 on the sorted array.
    // Tie at b == -a is branch-agnostic (both elu branches give 1).
#define SEARCH_P(na, p)                                                        \
    {                                                                          \
        int q = 0;                                                             \
        _Pragma("unroll")                                                      \
        for (int step = NGRID; step >= 1; step >>= 1)                          \
            if (q + step <= NGRID && sg[q + step - 1] <= (na)) q += step;      \
        (p) = q << 4;                                                          \
        _Pragma("unroll")                                                      \
        for (int step = 8; step >= 1; step >>= 1)                              \
            if ((p) + step <= P_PRO && sbp[(p) + step - 1] <= (na)) (p) += step; \
    }

    int i = start + c;
    // pairs: two independent search chains in flight (MLP=2)
    for (; i + 16 < end; i += 32) {
        const float* f1 = mol + i * HID;
        const float* f2 = mol + (i + 16) * HID;
        float a1 = sbmu[h], a2 = sbmu[h];
#pragma unroll
        for (int k = 0; k < HID; k++) {
            float wk = wm[k * HEADS + h];
            a1 = fmaf(__ldg(f1 + k), wk, a1);
            a2 = fmaf(__ldg(f2 + k), wk, a2);
        }
        float na1 = -a1, na2 = -a2;
        int p1, p2;
        SEARCH_P(na1, p1);
        SEARCH_P(na2, p2);
        float2 v1 = pr[p1], v2 = pr[p2];
        acc += (float)(P_PRO - p1) * (a1 + 1.f) + (totB - v1.x) + __expf(a1) * v1.y;
        acc += (float)(P_PRO - p2) * (a2 + 1.f) + (totB - v2.x) + __expf(a2) * v2.y;
    }
    if (i < end) {   // at most one leftover atom
        const float* f1 = mol + i * HID;
        float a1 = sbmu[h];
#pragma unroll
        for (int k = 0; k < HID; k++)
            a1 = fmaf(__ldg(f1 + k), wm[k * HEADS + h], a1);
        float na1 = -a1;
        int p1;
        SEARCH_P(na1, p1);
        float2 v1 = pr[p1];
        acc += (float)(P_PRO - p1) * (a1 + 1.f) + (totB - v1.x) + __expf(a1) * v1.y;
    }
#undef SEARCH_P
    part[t] = acc;
    __syncthreads();

    // reduce 16 chunks per head (fixed order -> deterministic)
    if (t < HEADS) {
        float s = 0.f;
        for (int c2 = 0; c2 < 16; c2++) s += part[c2 * HEADS + t];
        yg[t] = s * 0.001f;
    }
    __syncthreads();

    // MLP: elu(yg @ W1 + b1) @ W2 + b2
    if (t < 2 * HEADS) {
        float s = __ldg(b1 + t);
        for (int hh = 0; hh < HEADS; hh++)
            s = fmaf(yg[hh], __ldg(W1 + hh * 2 * HEADS + t), s);
        h2[t] = (s > 0.f) ? s : expm1f(s);
    }
    __syncthreads();

    if (t == 0) {
        float s = __ldg(b2);
        for (int j = 0; j < 2 * HEADS; j++)
            s = fmaf(h2[j], __ldg(W2 + j), s);
        out[g] = s;
    }
}

// ---------------- launch -----------------------------------------------------
extern "C" void kernel_launch(void* const* d_in, const int* in_sizes, int n_in,
                              void* d_out, int out_size) {
    const float* mol_feats   = (const float*)d_in[0];  // [2048,64]
    const float* fused_feats = (const float*)d_in[1];  // [2048,64]
    const float* Wmu         = (const float*)d_in[2];  // [128,16]
    const float* bmu         = (const float*)d_in[3];  // [16]
    const float* W1          = (const float*)d_in[4];  // [16,32]
    const float* b1          = (const float*)d_in[5];  // [32]
    const float* W2          = (const float*)d_in[6];  // [32,1]
    const float* b2          = (const float*)d_in[7];  // [1]
    const int*   batch_raw   = (const int*)d_in[8];    // int64 or int32 (device-detected)
    float*       out         = (float*)d_out;          // [64]

    head_kernel<<<HEADS, 1024>>>(fused_feats, Wmu);
    graph_kernel<<<NGRAPH, 256>>>(mol_feats, Wmu, bmu, batch_raw,
                                  W1, b1, W2, b2, out);
}

// round 15
// speedup vs baseline: 2.7522x; 2.7522x over previous
#include <cuda_runtime.h>
#include <cuda_bf16.h>
#include <math.h>

// Problem constants (fixed by reference)
#define N_MOL  2048
#define P_PRO  2048
#define HID    64
#define HEADS  16
#define NGRAPH 64
#define NGRID  128          // sampled-grid entries per head (every 16th element)
#define NCH    32           // atom chunks per head in graph_kernel (512 threads)

// ---------------- scratch (device globals; allocations are forbidden) -------
__device__ float  g_sortedB[HEADS][P_PRO];      // per-head ascending-sorted a_pro
__device__ float2 g_pref2[HEADS][P_PRO + 1];    // {prefix(b), prefix(exp b)} exclusive
__device__ float  g_grid[HEADS][NGRID];         // g_grid[h][i] = sorted[h][16i+15]

// Warp compare-exchange via shfl_xor for element whose index-bits[0:4] == lane.
__device__ __forceinline__ float cmpex_shfl(float v, int j, bool dir, int lane) {
    float p = __shfl_xor_sync(0xFFFFFFFF, v, j);
    bool lower = ((lane & j) == 0);
    return (lower == dir) ? fminf(v, p) : fmaxf(v, p);
}

// ============================================================================
// K1: one block per head. Coalesced warp-cooperative projection a_pro ->
// hybrid bitonic sort -> fp32 prefix sums + sampled grid. 1024 threads.
// Sort element mapping: thread t = w*32+lane holds ia = w*64+lane, ib = ia+32.
// Phases j<=16 via shfl, j==32 in-register, j>=64 via smem.
// ============================================================================
__global__ __launch_bounds__(1024, 1)
void head_kernel(const float* __restrict__ pro,      // [2048,64]
                 const float* __restrict__ Wmu) {    // [128,16] row-major
    const int h    = blockIdx.x;
    const int t    = threadIdx.x;
    const int lane = t & 31;
    const int w    = t >> 5;
    const int ia   = w * 64 + lane;
    const int ib   = ia + 32;

    __shared__ float wv[HID];
    __shared__ float sb[P_PRO];
    __shared__ float warpB[33];
    __shared__ float warpE[33];

    if (t < HID) wv[t] = Wmu[(HID + t) * HEADS + h];   // protein half of Wmu, col h
    __syncthreads();

    // --------- projection (coalesced): warp w computes rows w*64..w*64+63 ----
    {
        const float w0 = wv[lane];
        const float w1 = wv[lane + 32];
#pragma unroll 4
        for (int j = 0; j < 64; j++) {
            int r = w * 64 + j;
            const float* f = pro + r * HID;
            float part = fmaf(f[lane], w0, f[lane + 32] * w1);
            part += __shfl_xor_sync(0xFFFFFFFF, part, 16);
            part += __shfl_xor_sync(0xFFFFFFFF, part, 8);
            part += __shfl_xor_sync(0xFFFFFFFF, part, 4);
            part += __shfl_xor_sync(0xFFFFFFFF, part, 2);
            part += __shfl_xor_sync(0xFFFFFFFF, part, 1);
            if (lane == 0) sb[r] = part;
        }
    }
    __syncthreads();

    float a = sb[ia];
    float b = sb[ib];

    // ---------------- hybrid bitonic sort (ascending) ----------------------
    for (int k = 2; k <= P_PRO; k <<= 1) {
        const bool dira = ((ia & k) == 0);
        const bool dirb = ((ib & k) == 0);

        if (k >= 128) {
            // smem phases: j = k/2 down to 64
            sb[ia] = a; sb[ib] = b;
            __syncthreads();
            for (int j = k >> 1; j >= 64; j >>= 1) {
                int i   = ((t & ~(j - 1)) << 1) | (t & (j - 1));  // bit-j = 0
                int ixj = i | j;
                bool dir = ((i & k) == 0);
                float x = sb[i], y = sb[ixj];
                if ((x > y) == dir) { sb[i] = y; sb[ixj] = x; }
                __syncthreads();
            }
            a = sb[ia]; b = sb[ib];
        }
        if (k >= 64) {
            // j = 32: partner is this thread's other register (pair lower = ia)
            float lo = fminf(a, b), hi = fmaxf(a, b);
            a = dira ? lo : hi;
            b = dira ? hi : lo;
        }
        // j = min(k/2,16) .. 1 : shfl phases
        int j0 = (k >> 1) < 16 ? (k >> 1) : 16;
        for (int j = j0; j >= 1; j >>= 1) {
            a = cmpex_shfl(a, j, dira, lane);
            b = cmpex_shfl(b, j, dirb, lane);
        }
    }
    // sorted values: direct coalesced store to gmem (lanes write 128B runs)
    // and park in smem for the scan + grid sampling.
    g_sortedB[h][ia] = a;
    g_sortedB[h][ib] = b;
    sb[ia] = a; sb[ib] = b;
    __syncthreads();

    // ---------------- fp32 prefix sums of b and exp(b) ----------------------
    // Thread t owns elements 2t, 2t+1. Fixed structure -> deterministic.
    float b0 = sb[2 * t];
    float b1 = sb[2 * t + 1];
    float e0 = __expf(b0), e1 = __expf(b1);
    float tB = b0 + b1, tE = e0 + e1;

    float sB = tB, sE = tE;   // warp inclusive scan
#pragma unroll
    for (int d = 1; d < 32; d <<= 1) {
        float uB = __shfl_up_sync(0xFFFFFFFF, sB, d);
        float uE = __shfl_up_sync(0xFFFFFFFF, sE, d);
        if (lane >= d) { sB += uB; sE += uE; }
    }
    if (lane == 31) { warpB[w] = sB; warpE[w] = sE; }
    __syncthreads();
    if (w == 0) {
        float vB = warpB[lane], vE = warpE[lane];
#pragma unroll
        for (int d = 1; d < 32; d <<= 1) {
            float uB = __shfl_up_sync(0xFFFFFFFF, vB, d);
            float uE = __shfl_up_sync(0xFFFFFFFF, vE, d);
            if (lane >= d) { vB += uB; vE += uE; }
        }
        warpB[lane + 1] = vB;   // warpB[w+1] = inclusive sum of warps 0..w
        warpE[lane + 1] = vE;
        if (lane == 0) { warpB[0] = 0.f; warpE[0] = 0.f; }
    }
    __syncthreads();

    float offB = warpB[w] + (sB - tB);   // exclusive offset for this thread
    float offE = warpE[w] + (sE - tE);

    g_pref2[h][2 * t + 1] = make_float2(offB + b0,      offE + e0);
    g_pref2[h][2 * t + 2] = make_float2(offB + b0 + b1, offE + e0 + e1);
    if (t == 0) g_pref2[h][0] = make_float2(0.f, 0.f);

    if (t < NGRID)
        g_grid[h][t] = sb[t * 16 + 15];
}

// ============================================================================
// Two-level count p = #{j : b_j <= na}:
//   level 1: 8-step uniform search over the 128-sample smem grid
//            (grid[i] = max of 16-block i  =>  16q <= p <= 16q+15)
//   level 2: ONE L2 round trip: 4 independent float4 loads of the 16-element
//            window (64B-aligned) + predicate count.
// Tie at b == -a is branch-agnostic (both elu branches give 1).
// ============================================================================
__device__ __forceinline__ int search_count(const float* __restrict__ sg,
                                            const float* __restrict__ sbp,
                                            float na) {
    int q = 0;
#pragma unroll
    for (int step = NGRID; step >= 1; step >>= 1)
        if (q + step <= NGRID && sg[q + step - 1] <= na) q += step;
    if (q == NGRID) return P_PRO;
    const float4* s4 = reinterpret_cast<const float4*>(sbp + (q << 4));
    float4 w0 = s4[0], w1 = s4[1], w2 = s4[2], w3 = s4[3];
    int c = 0;
    c += (w0.x <= na) + (w0.y <= na) + (w0.z <= na) + (w0.w <= na);
    c += (w1.x <= na) + (w1.y <= na) + (w1.z <= na) + (w1.w <= na);
    c += (w2.x <= na) + (w2.y <= na) + (w2.z <= na) + (w2.w <= na);
    c += (w3.x <= na) + (w3.y <= na) + (w3.z <= na) + (w3.w <= na);
    return (q << 4) + c;
}

// ============================================================================
// K2: one block per graph, 512 threads (32 atom-chunks x 16 heads: each thread
// usually owns ONE atom -> minimal serial chain). Stages mol_batch + sampled
// grids in smem, finds the graph's contiguous atom range (smem search),
// computes a_mol inline (float4 feature loads, lane-broadcast), evaluates the
// closed form, segment-sums deterministically, applies the MLP head.
// ============================================================================
__global__ __launch_bounds__(512, 1)
void graph_kernel(const float* __restrict__ mol,       // [2048,64]
                  const float* __restrict__ Wmu,       // [128,16]
                  const float* __restrict__ bmu,       // [16]
                  const int*   __restrict__ raw,       // mol_batch (i32 or i64 words)
                  const float* __restrict__ W1,        // [16,32]
                  const float* __restrict__ b1,        // [32]
                  const float* __restrict__ W2,        // [32,1]
                  const float* __restrict__ b2,        // [1]
                  float*       __restrict__ out) {     // [64]
    const int g = blockIdx.x;
    const int t = threadIdx.x;

    __shared__ float wm[HID * HEADS];          // mol half of Wmu, [k*16+h]
    __shared__ float sgrid[HEADS * NGRID];     // sampled grids, 8KB
    __shared__ int   sbatch[N_MOL];            // batch ids, 8KB
    __shared__ float sbmu[HEADS];
    __shared__ float part[NCH * HEADS];        // 512
    __shared__ float yg[HEADS];
    __shared__ float h2[2 * HEADS];

    // int64 vs int32 layout of mol_batch: for little-endian int64, word 2047
    // is the high half of element 1023 (== 0, values are small non-negative);
    // for int32 it is the last (max) batch id, nonzero for this distribution.
    const bool is64 = (raw[N_MOL - 1] == 0);
    const int  stride = is64 ? 2 : 1;

    for (int i = t; i < HID * HEADS; i += 512) wm[i] = Wmu[i];
    for (int i = t; i < HEADS * NGRID; i += 512)
        sgrid[i] = ((const float*)g_grid)[i];
    for (int i = t; i < N_MOL; i += 512) sbatch[i] = raw[i * stride];
    if (t < HEADS) sbmu[t] = bmu[t];
    __syncthreads();

    // contiguous range [start, end) of atoms with batch == g (batch is sorted)
    int lo = 0, hi = N_MOL;
    while (lo < hi) { int m = (lo + hi) >> 1; if (sbatch[m] < g) lo = m + 1; else hi = m; }
    const int start = lo;
    lo = start; hi = N_MOL;
    while (lo < hi) { int m = (lo + hi) >> 1; if (sbatch[m] < g + 1) lo = m + 1; else hi = m; }
    const int end = lo;

    // y_atom closed form. Thread t: head h = t&15, atom chunk c = t>>4.
    const int h = t & (HEADS - 1);
    const int c = t >> 4;                      // 0..31
    float acc = 0.f;
    const float*  sbp = g_sortedB[h];
    const float2* pr  = g_pref2[h];
    const float*  sg  = sgrid + h * NGRID;
    const float   totB = pr[P_PRO].x;

    for (int i = start + c; i < end; i += NCH) {
        // feature row via 16 independent float4 loads (lane-broadcast friendly)
        const float4* f4 = reinterpret_cast<const float4*>(mol + i * HID);
        float a = sbmu[h];
#pragma unroll
        for (int k4 = 0; k4 < HID / 4; k4++) {
            float4 fv = __ldg(f4 + k4);
            const float* wr = wm + (k4 * 4) * HEADS + h;
            a = fmaf(fv.x, wr[0 * HEADS], a);
            a = fmaf(fv.y, wr[1 * HEADS], a);
            a = fmaf(fv.z, wr[2 * HEADS], a);
            a = fmaf(fv.w, wr[3 * HEADS], a);
        }
        int p = search_count(sg, sbp, -a);
        float2 v = pr[p];
        acc += (float)(P_PRO - p) * (a + 1.f) + (totB - v.x) + __expf(a) * v.y;
    }
    part[t] = acc;
    __syncthreads();

    // reduce 32 chunks per head (fixed order -> deterministic)
    if (t < HEADS) {
        float s = 0.f;
        for (int c2 = 0; c2 < NCH; c2++) s += part[c2 * HEADS + t];
        yg[t] = s * 0.001f;
    }
    __syncthreads();

    // MLP: elu(yg @ W1 + b1) @ W2 + b2
    if (t < 2 * HEADS) {
        float s = __ldg(b1 + t);
        for (int hh = 0; hh < HEADS; hh++)
            s = fmaf(yg[hh], __ldg(W1 + hh * 2 * HEADS + t), s);
        h2[t] = (s > 0.f) ? s : expm1f(s);
    }
    __syncthreads();

    if (t == 0) {
        float s = __ldg(b2);
        for (int j = 0; j < 2 * HEADS; j++)
            s = fmaf(h2[j], __ldg(W2 + j), s);
        out[g] = s;
    }
}

// ---------------- launch -----------------------------------------------------
extern "C" void kernel_launch(void* const* d_in, const int* in_sizes, int n_in,
                              void* d_out, int out_size) {
    const float* mol_feats   = (const float*)d_in[0];  // [2048,64]
    const float* fused_feats = (const float*)d_in[1];  // [2048,64]
    const float* Wmu         = (const float*)d_in[2];  // [128,16]
    const float* bmu         = (const float*)d_in[3];  // [16]
    const float* W1          = (const float*)d_in[4];  // [16,32]
    const float* b1          = (const float*)d_in[5];  // [32]
    const float* W2          = (const float*)d_in[6];  // [32,1]
    const float* b2          = (const float*)d_in[7];  // [1]
    const int*   batch_raw   = (const int*)d_in[8];    // int64 or int32 (device-detected)
    float*       out         = (float*)d_out;          // [64]

    head_kernel<<<HEADS, 1024>>>(fused_feats, Wmu);
    graph_kernel<<<NGRAPH, 512>>>(mol_feats, Wmu, bmu, batch_raw,
                                  W1, b1, W2, b2, out);
}